// round 7
// baseline (speedup 1.0000x reference)
#include <cuda_runtime.h>
#include <math.h>

#define B_ 256
#define T_ 1024
#define V_ 96
#define H_ 128

typedef unsigned long long ull;

// Device-global scratch (allocation-free per harness rules)
__device__ __align__(16) float g_proj[V_ * H_];       // emb @ W_ih0^T + b_ih0 + b_hh0
__device__ __align__(16) float g_y0[B_ * T_ * H_];    // layer-0 outputs
__device__ __align__(16) float g_xp1[B_ * T_ * H_];   // y0 @ W_ih1^T + b_ih1 + b_hh1
__device__ __align__(16) float g_y1[B_ * T_ * H_];    // layer-1 outputs

// packed fp32x2 ops (Blackwell FFMA2 / FADD2)
__device__ __forceinline__ ull ffma2(ull a, ull b, ull c) {
    ull d;
    asm("fma.rn.f32x2 %0, %1, %2, %3;" : "=l"(d) : "l"(a), "l"(b), "l"(c));
    return d;
}
__device__ __forceinline__ float hadd(ull a) {
    float x, y;
    asm("mov.b64 {%0, %1}, %2;" : "=f"(x), "=f"(y) : "l"(a));
    return x + y;
}
__device__ __forceinline__ float tanh_fast(float x) {
    float y;
    asm("tanh.approx.f32 %0, %1;" : "=f"(y) : "f"(x));
    return y;
}

// ---------------------------------------------------------------------------
// Projected embedding table: g_proj[v][j] = sum_h emb[v][h]*W_ih0[j][h] + b
// ---------------------------------------------------------------------------
__global__ void k_proj(const float* __restrict__ emb, const float* __restrict__ Wih0,
                       const float* __restrict__ bih0, const float* __restrict__ bhh0) {
    __shared__ float er[H_];
    int v = blockIdx.x, j = threadIdx.x;
    er[j] = emb[v * H_ + j];
    __syncthreads();
    float s = bih0[j] + bhh0[j];
    const float* wr = Wih0 + j * H_;
#pragma unroll 8
    for (int h = 0; h < H_; h++) s += er[h] * wr[h];
    g_proj[v * H_ + j] = s;
}

// ---------------------------------------------------------------------------
// Recurrence: 128 thr/CTA, 1 batch/CTA, grid=B. Thread (g=tid>>2, ks=tid&3)
// owns 4 W rows x 32 k in regs: 8 LDS.128 feed 64 FFMA2 (8:1 MAC/load).
// ks-reduce via 2 shfl.bfly rounds; lane ks finishes row 4g+ks == tid.
// y stores batched via 16-deep smem ring, dumped every 8 steps (coalesced).
// ---------------------------------------------------------------------------
__device__ __forceinline__ void load_w4(const float* __restrict__ W, int g, int ks, ull* w) {
    const ull* Wp = (const ull*)W;   // pair units, row stride 64
#pragma unroll
    for (int r = 0; r < 4; r++) {
        const ull* row = Wp + (4 * g + r) * 64 + ks * 16;
#pragma unroll
        for (int p = 0; p < 16; p++) w[r * 16 + p] = row[p];
    }
}

__device__ __forceinline__ float step_dot4(const float* __restrict__ hbuf, int ks, const ull* w) {
    const ulonglong2* h2 = (const ulonglong2*)hbuf + ks * 8;
    ull a0 = 0, a1 = 0, a2 = 0, a3 = 0;
#pragma unroll
    for (int i = 0; i < 8; i++) {
        ulonglong2 hv = h2[i];
        a0 = ffma2(w[0  + 2 * i],     hv.x, a0);
        a1 = ffma2(w[16 + 2 * i],     hv.x, a1);
        a2 = ffma2(w[32 + 2 * i],     hv.x, a2);
        a3 = ffma2(w[48 + 2 * i],     hv.x, a3);
        a0 = ffma2(w[0  + 2 * i + 1], hv.y, a0);
        a1 = ffma2(w[16 + 2 * i + 1], hv.y, a1);
        a2 = ffma2(w[32 + 2 * i + 1], hv.y, a2);
        a3 = ffma2(w[48 + 2 * i + 1], hv.y, a3);
    }
    float p0 = hadd(a0), p1 = hadd(a1), p2 = hadd(a2), p3 = hadd(a3);
    p0 += __shfl_xor_sync(0xffffffffu, p0, 1);
    p1 += __shfl_xor_sync(0xffffffffu, p1, 1);
    p2 += __shfl_xor_sync(0xffffffffu, p2, 1);
    p3 += __shfl_xor_sync(0xffffffffu, p3, 1);
    p0 += __shfl_xor_sync(0xffffffffu, p0, 2);
    p1 += __shfl_xor_sync(0xffffffffu, p1, 2);
    p2 += __shfl_xor_sync(0xffffffffu, p2, 2);
    p3 += __shfl_xor_sync(0xffffffffu, p3, 2);
    return (ks == 0) ? p0 : (ks == 1) ? p1 : (ks == 2) ? p2 : p3;
}

__global__ void __launch_bounds__(128, 2)
k_l0(const int* __restrict__ x, const float* __restrict__ Whh0, float* __restrict__ hid0) {
    __shared__ __align__(16) float h_s[2][128];
    __shared__ __align__(16) float hist[16][128];
    __shared__ int x_s[T_];

    int tid = threadIdx.x;
    int ks = tid & 3, g = tid >> 2;
    int b = blockIdx.x;

    ull w[64];
    load_w4(Whh0, g, ks, w);

    for (int i = tid; i < T_; i += 128) x_s[i] = x[b * T_ + i];
    h_s[0][tid] = 0.0f;
    __syncthreads();

    float p_cur = g_proj[x_s[0] * H_ + tid];
    float p_nxt = g_proj[x_s[1] * H_ + tid];

    int ds = tid >> 4, dc = (tid & 15) * 8;   // dump role
    float nh = 0.0f;
    for (int t = 0; t < T_; t++) {
        float p = step_dot4(h_s[t & 1], ks, w);

        nh = tanh_fast(p + p_cur);
        h_s[(t + 1) & 1][tid] = nh;
        hist[t & 15][tid] = nh;

        p_cur = p_nxt;
        int tn = (t + 2 < T_) ? (t + 2) : (T_ - 1);
        p_nxt = g_proj[x_s[tn] * H_ + tid];
        __syncthreads();

        if ((t & 7) == 7) {                   // coalesced 8-step dump
            int oct = (t >> 3) & 1;
            const float4* src = (const float4*)&hist[oct * 8 + ds][dc];
            float4 v0 = src[0], v1 = src[1];
            float4* dst = (float4*)&g_y0[((size_t)b * T_ + (t - 7 + ds)) * H_ + dc];
            dst[0] = v0; dst[1] = v1;
        }
    }
    hid0[b * H_ + tid] = nh;
}

__global__ void __launch_bounds__(128, 2)
k_l1(const float* __restrict__ Whh1, float* __restrict__ hid1) {
    __shared__ __align__(16) float h_s[2][128];
    __shared__ __align__(16) float hist[16][128];

    int tid = threadIdx.x;
    int ks = tid & 3, g = tid >> 2;
    int b = blockIdx.x;

    ull w[64];
    load_w4(Whh1, g, ks, w);

    h_s[0][tid] = 0.0f;
    __syncthreads();

    const float* xp = g_xp1 + (size_t)b * T_ * H_ + tid;
    float p_cur = xp[0];
    float p_nxt = xp[H_];

    int ds = tid >> 4, dc = (tid & 15) * 8;
    float nh = 0.0f;
    for (int t = 0; t < T_; t++) {
        float p = step_dot4(h_s[t & 1], ks, w);

        nh = tanh_fast(p + p_cur);
        h_s[(t + 1) & 1][tid] = nh;
        hist[t & 15][tid] = nh;

        p_cur = p_nxt;
        int tn = (t + 2 < T_) ? (t + 2) : (T_ - 1);
        p_nxt = xp[(size_t)tn * H_];
        __syncthreads();

        if ((t & 7) == 7) {
            int oct = (t >> 3) & 1;
            const float4* src = (const float4*)&hist[oct * 8 + ds][dc];
            float4 v0 = src[0], v1 = src[1];
            float4* dst = (float4*)&g_y1[((size_t)b * T_ + (t - 7 + ds)) * H_ + dc];
            dst[0] = v0; dst[1] = v1;
        }
    }
    hid1[b * H_ + tid] = nh;
}

// ---------------------------------------------------------------------------
// FFMA2 GEMM: out[r][v] = sum_h in[r][h]*W[v][h] + b1[v] (+ b2[v])
// 64 rows x N cols per CTA, 256 threads, 2 CTAs/SM.
// W^T staged in smem [kp][N+1] (pad -> conflict-free compute loads).
// ---------------------------------------------------------------------------
template <int N>
__global__ void __launch_bounds__(256, 2)
k_gemm(const float* __restrict__ in, const float* __restrict__ W,
       const float* __restrict__ b1, const float* __restrict__ b2,
       float* __restrict__ out) {
    constexpr int NP = N + 1;
    extern __shared__ ull sm[];
    ull* Ws = sm;                 // [64 kp][NP]
    ull* ys = sm + 64 * NP;       // [64 rows][64 kp]
    int tid = threadIdx.x;

    const ull* Wg = (const ull*)W;
    for (int i = tid; i < N * 64; i += 256) {
        int v = i >> 6, kp = i & 63;
        Ws[kp * NP + v] = Wg[i];
    }
    const ull* yg = (const ull*)in + (size_t)blockIdx.x * 64 * 64;
    for (int i = tid; i < 64 * 64; i += 256) ys[i] = yg[i];
    __syncthreads();

    constexpr int CJ = N / 16;    // cols per thread: 6 (N=96) or 8 (N=128)
    int tx = tid & 15, ty = tid >> 4;
    int r0 = ty * 4;

    ull acc[4][CJ];
#pragma unroll
    for (int ii = 0; ii < 4; ii++)
#pragma unroll
        for (int jj = 0; jj < CJ; jj++) acc[ii][jj] = 0;

#pragma unroll 2
    for (int kp = 0; kp < 64; kp++) {
        ull yv[4], wv[CJ];
#pragma unroll
        for (int ii = 0; ii < 4; ii++) yv[ii] = ys[(r0 + ii) * 64 + kp];     // broadcast
#pragma unroll
        for (int jj = 0; jj < CJ; jj++) wv[jj] = Ws[kp * NP + tx + 16 * jj]; // conflict-free
#pragma unroll
        for (int ii = 0; ii < 4; ii++)
#pragma unroll
            for (int jj = 0; jj < CJ; jj++)
                acc[ii][jj] = ffma2(yv[ii], wv[jj], acc[ii][jj]);
    }

    float bias[CJ];
#pragma unroll
    for (int jj = 0; jj < CJ; jj++) {
        bias[jj] = b1[tx + 16 * jj];
        if (b2) bias[jj] += b2[tx + 16 * jj];
    }

    size_t row0 = (size_t)blockIdx.x * 64 + r0;
#pragma unroll
    for (int ii = 0; ii < 4; ii++)
#pragma unroll
        for (int jj = 0; jj < CJ; jj++)
            out[(row0 + ii) * N + tx + 16 * jj] = hadd(acc[ii][jj]) + bias[jj];
}

// ---------------------------------------------------------------------------
extern "C" void kernel_launch(void* const* d_in, const int* in_sizes, int n_in,
                              void* d_out, int out_size) {
    const int*   x    = (const int*)d_in[0];
    const float* emb  = (const float*)d_in[1];
    const float* Wih0 = (const float*)d_in[2];
    const float* Whh0 = (const float*)d_in[3];
    const float* bih0 = (const float*)d_in[4];
    const float* bhh0 = (const float*)d_in[5];
    const float* Wih1 = (const float*)d_in[6];
    const float* Whh1 = (const float*)d_in[7];
    const float* bih1 = (const float*)d_in[8];
    const float* bhh1 = (const float*)d_in[9];
    const float* fcW  = (const float*)d_in[10];
    const float* fcb  = (const float*)d_in[11];

    float* out = (float*)d_out;
    float* hid = out + (size_t)B_ * T_ * V_;   // hidden [2,B,H] after logits

    float* y0p;  cudaGetSymbolAddress((void**)&y0p,  g_y0);
    float* xp1p; cudaGetSymbolAddress((void**)&xp1p, g_xp1);
    float* y1p;  cudaGetSymbolAddress((void**)&y1p,  g_y1);

    const int smem_xp = (64 * 129 + 64 * 64) * 8;   // 98,816 B
    const int smem_fc = (64 * 97  + 64 * 64) * 8;   // 82,432 B
    cudaFuncSetAttribute(k_gemm<128>, cudaFuncAttributeMaxDynamicSharedMemorySize, smem_xp);
    cudaFuncSetAttribute(k_gemm<96>,  cudaFuncAttributeMaxDynamicSharedMemorySize, smem_fc);

    k_proj<<<V_, H_>>>(emb, Wih0, bih0, bhh0);
    k_l0<<<B_, 128>>>(x, Whh0, hid);
    k_gemm<128><<<(B_ * T_) / 64, 256, smem_xp>>>(y0p, Wih1, bih1, bhh1, xp1p);
    k_l1<<<B_, 128>>>(Whh1, hid + B_ * H_);
    k_gemm<96><<<(B_ * T_) / 64, 256, smem_fc>>>(y1p, fcW, fcb, nullptr, out);
}

// round 8
// speedup vs baseline: 1.6806x; 1.6806x over previous
#include <cuda_runtime.h>
#include <cuda_bf16.h>
#include <math.h>

#define B_ 256
#define T_ 1024
#define V_ 96
#define H_ 128

typedef unsigned long long ull;
typedef unsigned int uint;

// Device-global scratch (allocation-free per harness rules)
__device__ __align__(16) float g_proj[V_ * H_];       // emb @ W_ih0^T + b_ih0 + b_hh0
__device__ __align__(16) float g_y0[B_ * T_ * H_];    // layer-0 outputs
__device__ __align__(16) float g_xp1[B_ * T_ * H_];   // y0 @ W_ih1^T + b_ih1 + b_hh1
__device__ __align__(16) float g_y1[B_ * T_ * H_];    // layer-1 outputs

// packed fp32x2 ops (Blackwell FFMA2 / FADD2)
__device__ __forceinline__ ull ffma2(ull a, ull b, ull c) {
    ull d;
    asm("fma.rn.f32x2 %0, %1, %2, %3;" : "=l"(d) : "l"(a), "l"(b), "l"(c));
    return d;
}
__device__ __forceinline__ float hadd(ull a) {
    float x, y;
    asm("mov.b64 {%0, %1}, %2;" : "=f"(x), "=f"(y) : "l"(a));
    return x + y;
}
__device__ __forceinline__ float tanh_fast(float x) {
    float y;
    asm("tanh.approx.f32 %0, %1;" : "=f"(y) : "f"(x));
    return y;
}

// ---------------------------------------------------------------------------
// Projected embedding table: g_proj[v][j] = sum_h emb[v][h]*W_ih0[j][h] + b
// ---------------------------------------------------------------------------
__global__ void k_proj(const float* __restrict__ emb, const float* __restrict__ Wih0,
                       const float* __restrict__ bih0, const float* __restrict__ bhh0) {
    __shared__ float er[H_];
    int v = blockIdx.x, j = threadIdx.x;
    er[j] = emb[v * H_ + j];
    __syncthreads();
    float s = bih0[j] + bhh0[j];
    const float* wr = Wih0 + j * H_;
#pragma unroll 8
    for (int h = 0; h < H_; h++) s += er[h] * wr[h];
    g_proj[v * H_ + j] = s;
}

// ---------------------------------------------------------------------------
// Recurrence (R4 structure, verbatim): thread j owns full W row j (64 ull).
// One barrier/step; y store after the barrier; addend 2-deep reg prefetch.
// ---------------------------------------------------------------------------
__global__ void __launch_bounds__(128, 3)
k_l0(const int* __restrict__ x, const float* __restrict__ Whh0, float* __restrict__ hid0) {
    __shared__ __align__(16) float h_s[2][128];
    __shared__ int x_s[T_];

    int j = threadIdx.x;
    int b = blockIdx.x;

    ull w[64];
    const ull* Wp = (const ull*)Whh0 + j * 64;
#pragma unroll
    for (int i = 0; i < 64; i++) w[i] = Wp[i];

    for (int i = j; i < T_; i += 128) x_s[i] = x[b * T_ + i];
    h_s[0][j] = 0.0f;
    __syncthreads();

    float p_cur = g_proj[x_s[0] * H_ + j];
    float p_nxt = g_proj[x_s[1] * H_ + j];

    float nh = 0.0f;
    for (int t = 0; t < T_; t++) {
        const ulonglong2* h2 = (const ulonglong2*)h_s[t & 1];
        ull a0 = 0, a1 = 0, a2 = 0, a3 = 0;
#pragma unroll
        for (int i = 0; i < 32; i += 2) {
            ulonglong2 hv = h2[i];
            a0 = ffma2(w[2 * i],     hv.x, a0);
            a1 = ffma2(w[2 * i + 1], hv.y, a1);
            ulonglong2 hw = h2[i + 1];
            a2 = ffma2(w[2 * i + 2], hw.x, a2);
            a3 = ffma2(w[2 * i + 3], hw.y, a3);
        }
        ull s01, s23, s;
        asm("add.rn.f32x2 %0, %1, %2;" : "=l"(s01) : "l"(a0), "l"(a1));
        asm("add.rn.f32x2 %0, %1, %2;" : "=l"(s23) : "l"(a2), "l"(a3));
        asm("add.rn.f32x2 %0, %1, %2;" : "=l"(s)   : "l"(s01), "l"(s23));
        float p = hadd(s);

        nh = tanh_fast(p + p_cur);
        h_s[(t + 1) & 1][j] = nh;

        p_cur = p_nxt;
        int tn = (t + 2 < T_) ? (t + 2) : (T_ - 1);
        p_nxt = g_proj[x_s[tn] * H_ + j];
        __syncthreads();
        g_y0[((size_t)b * T_ + t) * H_ + j] = nh;   // post-barrier store
    }
    hid0[b * H_ + j] = nh;
}

__global__ void __launch_bounds__(128, 3)
k_l1(const float* __restrict__ Whh1, float* __restrict__ hid1) {
    __shared__ __align__(16) float h_s[2][128];

    int j = threadIdx.x;
    int b = blockIdx.x;

    ull w[64];
    const ull* Wp = (const ull*)Whh1 + j * 64;
#pragma unroll
    for (int i = 0; i < 64; i++) w[i] = Wp[i];

    h_s[0][j] = 0.0f;
    __syncthreads();

    const float* xp = g_xp1 + (size_t)b * T_ * H_ + j;
    float p_cur = xp[0];
    float p_nxt = xp[H_];

    float nh = 0.0f;
    for (int t = 0; t < T_; t++) {
        const ulonglong2* h2 = (const ulonglong2*)h_s[t & 1];
        ull a0 = 0, a1 = 0, a2 = 0, a3 = 0;
#pragma unroll
        for (int i = 0; i < 32; i += 2) {
            ulonglong2 hv = h2[i];
            a0 = ffma2(w[2 * i],     hv.x, a0);
            a1 = ffma2(w[2 * i + 1], hv.y, a1);
            ulonglong2 hw = h2[i + 1];
            a2 = ffma2(w[2 * i + 2], hw.x, a2);
            a3 = ffma2(w[2 * i + 3], hw.y, a3);
        }
        ull s01, s23, s;
        asm("add.rn.f32x2 %0, %1, %2;" : "=l"(s01) : "l"(a0), "l"(a1));
        asm("add.rn.f32x2 %0, %1, %2;" : "=l"(s23) : "l"(a2), "l"(a3));
        asm("add.rn.f32x2 %0, %1, %2;" : "=l"(s)   : "l"(s01), "l"(s23));
        float p = hadd(s);

        nh = tanh_fast(p + p_cur);
        h_s[(t + 1) & 1][j] = nh;

        p_cur = p_nxt;
        int tn = (t + 2 < T_) ? (t + 2) : (T_ - 1);
        p_nxt = xp[(size_t)tn * H_];
        __syncthreads();
        g_y1[((size_t)b * T_ + t) * H_ + j] = nh;   // post-barrier store
    }
    hid1[b * H_ + j] = nh;
}

// ---------------------------------------------------------------------------
// Tensor-core GEMM via mma.sync m16n8k16 bf16, split-bf16 3-term (exact to
// ~1e-5): C = Yhi@Whi^T + Yhi@Wlo^T + Ylo@Whi^T.
// out[r][n] = sum_k in[r][k] * W[n][k] + b1[n] (+ b2[n]).
// CTA: 64 rows x N cols, 256 thr (8 warps = 2 m-groups x 4 n-groups).
// smem: k-pair-packed bf16x2 tiles, row stride 68 (frag loads hit 32 banks).
// ---------------------------------------------------------------------------
__device__ __forceinline__ void mma16816(float* c, const uint* a, uint b0, uint b1) {
    asm volatile(
        "mma.sync.aligned.m16n8k16.row.col.f32.bf16.bf16.f32 "
        "{%0,%1,%2,%3}, {%4,%5,%6,%7}, {%8,%9}, {%0,%1,%2,%3};"
        : "+f"(c[0]), "+f"(c[1]), "+f"(c[2]), "+f"(c[3])
        : "r"(a[0]), "r"(a[1]), "r"(a[2]), "r"(a[3]), "r"(b0), "r"(b1));
}

__device__ __forceinline__ void split_pack(float2 v, uint& hi, uint& lo) {
    __nv_bfloat16 h0 = __float2bfloat16_rn(v.x);
    __nv_bfloat16 h1 = __float2bfloat16_rn(v.y);
    float r0 = v.x - __bfloat162float(h0);
    float r1 = v.y - __bfloat162float(h1);
    __nv_bfloat162 hp; hp.x = h0; hp.y = h1;
    __nv_bfloat162 lp = __floats2bfloat162_rn(r0, r1);
    hi = *(uint*)&hp;
    lo = *(uint*)&lp;
}

template <int N>
__global__ void __launch_bounds__(256, 2)
k_tgemm(const float* __restrict__ in, const float* __restrict__ W,
        const float* __restrict__ b1, const float* __restrict__ b2,
        float* __restrict__ out) {
    constexpr int NTW = N / 32;          // n8-tiles per warp: 4 (N=128) / 3 (N=96)
    constexpr int ST = 68;               // smem row stride (b32 units)
    extern __shared__ uint sm[];
    uint* whi = sm;                      // [N][ST]
    uint* wlo = whi + N * ST;
    uint* yhi = wlo + N * ST;            // [64][ST]
    uint* ylo = yhi + 64 * ST;

    int tid = threadIdx.x;
    size_t row0 = (size_t)blockIdx.x * 64;

    // Stage W: [N][128] fp32 -> hi/lo bf16 pairs [N][64 k2]
    const float2* Wg = (const float2*)W;
    for (int i = tid; i < N * 64; i += 256) {
        int n = i >> 6, k2 = i & 63;
        uint h, l;
        split_pack(Wg[i], h, l);
        whi[n * ST + k2] = h;
        wlo[n * ST + k2] = l;
    }
    // Stage Y tile: [64][128] fp32 -> hi/lo pairs
    const float2* Yg = (const float2*)(in + row0 * H_);
    for (int i = tid; i < 64 * 64; i += 256) {
        int r = i >> 6, k2 = i & 63;
        uint h, l;
        split_pack(Yg[i], h, l);
        yhi[r * ST + k2] = h;
        ylo[r * ST + k2] = l;
    }
    __syncthreads();

    int wid = tid >> 5, lane = tid & 31;
    int g = lane >> 2, t = lane & 3;
    int mg = wid & 1;                    // m-group: rows 32*mg .. +32
    int ng = wid >> 1;                   // n-group: cols ng*8*NTW .. +8*NTW

    float c[2][NTW][4];
#pragma unroll
    for (int mt = 0; mt < 2; mt++)
#pragma unroll
        for (int nt = 0; nt < NTW; nt++)
#pragma unroll
            for (int q = 0; q < 4; q++) c[mt][nt][q] = 0.0f;

#pragma unroll
    for (int ki = 0; ki < 8; ki++) {
        int kb = ki * 8;
        uint ahi[2][4], alo[2][4];
#pragma unroll
        for (int mt = 0; mt < 2; mt++) {
            int r = mg * 32 + mt * 16;
            ahi[mt][0] = yhi[(r + g) * ST + kb + t];
            ahi[mt][1] = yhi[(r + 8 + g) * ST + kb + t];
            ahi[mt][2] = yhi[(r + g) * ST + kb + 4 + t];
            ahi[mt][3] = yhi[(r + 8 + g) * ST + kb + 4 + t];
            alo[mt][0] = ylo[(r + g) * ST + kb + t];
            alo[mt][1] = ylo[(r + 8 + g) * ST + kb + t];
            alo[mt][2] = ylo[(r + g) * ST + kb + 4 + t];
            alo[mt][3] = ylo[(r + 8 + g) * ST + kb + 4 + t];
        }
#pragma unroll
        for (int nt = 0; nt < NTW; nt++) {
            int n = ng * (8 * NTW) + nt * 8;
            uint bh0 = whi[(n + g) * ST + kb + t];
            uint bh1 = whi[(n + g) * ST + kb + 4 + t];
            uint bl0 = wlo[(n + g) * ST + kb + t];
            uint bl1 = wlo[(n + g) * ST + kb + 4 + t];
#pragma unroll
            for (int mt = 0; mt < 2; mt++) {
                mma16816(c[mt][nt], ahi[mt], bh0, bh1);   // hi*hi
                mma16816(c[mt][nt], ahi[mt], bl0, bl1);   // hi*lo
                mma16816(c[mt][nt], alo[mt], bh0, bh1);   // lo*hi
            }
        }
    }

    // Epilogue: c mapping -> out[row0 + 32mg + 16mt + g (+8)][n + 2t (+1)]
#pragma unroll
    for (int nt = 0; nt < NTW; nt++) {
        int n = ng * (8 * NTW) + nt * 8 + 2 * t;
        float bx = b1[n], by = b1[n + 1];
        if (b2) { bx += b2[n]; by += b2[n + 1]; }
#pragma unroll
        for (int mt = 0; mt < 2; mt++) {
            size_t r = row0 + mg * 32 + mt * 16 + g;
            float2* o0 = (float2*)(out + r * N + n);
            float2* o1 = (float2*)(out + (r + 8) * N + n);
            *o0 = make_float2(c[mt][nt][0] + bx, c[mt][nt][1] + by);
            *o1 = make_float2(c[mt][nt][2] + bx, c[mt][nt][3] + by);
        }
    }
}

// ---------------------------------------------------------------------------
extern "C" void kernel_launch(void* const* d_in, const int* in_sizes, int n_in,
                              void* d_out, int out_size) {
    const int*   x    = (const int*)d_in[0];
    const float* emb  = (const float*)d_in[1];
    const float* Wih0 = (const float*)d_in[2];
    const float* Whh0 = (const float*)d_in[3];
    const float* bih0 = (const float*)d_in[4];
    const float* bhh0 = (const float*)d_in[5];
    const float* Wih1 = (const float*)d_in[6];
    const float* Whh1 = (const float*)d_in[7];
    const float* bih1 = (const float*)d_in[8];
    const float* bhh1 = (const float*)d_in[9];
    const float* fcW  = (const float*)d_in[10];
    const float* fcb  = (const float*)d_in[11];

    float* out = (float*)d_out;
    float* hid = out + (size_t)B_ * T_ * V_;   // hidden [2,B,H] after logits

    float* y0p;  cudaGetSymbolAddress((void**)&y0p,  g_y0);
    float* xp1p; cudaGetSymbolAddress((void**)&xp1p, g_xp1);
    float* y1p;  cudaGetSymbolAddress((void**)&y1p,  g_y1);

    const int smem_xp = (2 * 128 + 2 * 64) * 68 * 4;   // 104,448 B
    const int smem_fc = (2 * 96  + 2 * 64) * 68 * 4;   //  87,040 B
    cudaFuncSetAttribute(k_tgemm<128>, cudaFuncAttributeMaxDynamicSharedMemorySize, smem_xp);
    cudaFuncSetAttribute(k_tgemm<96>,  cudaFuncAttributeMaxDynamicSharedMemorySize, smem_fc);

    k_proj<<<V_, H_>>>(emb, Wih0, bih0, bhh0);
    k_l0<<<B_, 128>>>(x, Whh0, hid);
    k_tgemm<128><<<(B_ * T_) / 64, 256, smem_xp>>>(y0p, Wih1, bih1, bhh1, xp1p);
    k_l1<<<B_, 128>>>(Whh1, hid + B_ * H_);
    k_tgemm<96><<<(B_ * T_) / 64, 256, smem_fc>>>(y1p, fcW, fcb, nullptr, out);
}